// round 8
// baseline (speedup 1.0000x reference)
#include <cuda_runtime.h>
#include <cuda_fp16.h>

#define N_INST 200000
#define N_NETN 50000
#define NN     250000
#define NE     2000000
#define NSCANB 245   // ceil(250000/1024)

// ---------------- device scratch (no runtime allocation allowed) ----------------
__device__ float   g_xf[(size_t)NN * 64];     // x_f = h @ Wf + bf (fp32, self term)
__device__ float   g_xr[(size_t)NN * 64];     // x_r = h @ Wr + br
__device__ __half2 g_yf[(size_t)NN * 32];     // relu(x_f) fp16 (gather payload)
__device__ __half2 g_yr[(size_t)NN * 32];     // relu(x_r) fp16
__device__ float   g_tmp[(size_t)N_INST * 128]; // encoder hidden (inst)
__device__ float   g_tmpn[(size_t)N_NETN * 64]; // encoder hidden (net)
__device__ float   g_disf[NN], g_disr[NN];    // deg^-1/2
__device__ float   g_idegf[NN], g_idegr[NN];  // deg^-1
__device__ int     g_cntf[NN], g_cntr[NN];    // edge counts (row / col)
__device__ int     g_offF[NN], g_offR[NN];    // CSR bucket starts
__device__ int     g_fillF[NN], g_fillR[NN];
__device__ int     g_bsF[256], g_bsR[256];    // scan block sums
__device__ int2    g_csrF[NE];                // (src, norm) bucketed by col
__device__ int2    g_csrR[NE];                // (src, norm) bucketed by row

// ---------------- helpers ----------------
__device__ __forceinline__ float leaky(float v) { return fmaxf(v, 0.1f * v); }

__device__ __forceinline__ unsigned long long dup64(float a) {
    unsigned long long r;
    asm("mov.b64 %0, {%1, %1};" : "=l"(r) : "f"(a));
    return r;
}
__device__ __forceinline__ float2 up64(unsigned long long v) {
    float2 r;
    asm("mov.b64 {%0, %1}, %2;" : "=f"(r.x), "=f"(r.y) : "l"(v));
    return r;
}
__device__ __forceinline__ void fma2(unsigned long long& d,
                                     unsigned long long a,
                                     unsigned long long b) {
    asm("fma.rn.f32x2 %0, %1, %2, %0;" : "+l"(d) : "l"(a), "l"(b));
}

// ---------------- degree counting ----------------
__global__ __launch_bounds__(256) void k_count(const int* __restrict__ ei) {
    int e = blockIdx.x * 256 + threadIdx.x;
    if (e >= NE) return;
    atomicAdd(&g_cntf[ei[e]], 1);
    atomicAdd(&g_cntr[ei[NE + e]], 1);
}

__global__ __launch_bounds__(256) void k_deg() {
    int n = blockIdx.x * 256 + threadIdx.x;
    if (n >= NN) return;
    float df = (float)g_cntf[n] + 1.0f;
    float dr = (float)g_cntr[n] + 1.0f;
    g_disf[n] = rsqrtf(df);
    g_disr[n] = rsqrtf(dr);
    g_idegf[n] = 1.0f / df;
    g_idegr[n] = 1.0f / dr;
}

// ---------------- exclusive scan ----------------
__global__ __launch_bounds__(256) void k_scan1(const int* __restrict__ cnt,
                                               int* __restrict__ off,
                                               int* __restrict__ bsum) {
    __shared__ int wsum[8];
    int tid = threadIdx.x, lane = tid & 31, w = tid >> 5;
    int base = blockIdx.x * 1024 + tid * 4;
    int v0 = (base + 0 < NN) ? cnt[base + 0] : 0;
    int v1 = (base + 1 < NN) ? cnt[base + 1] : 0;
    int v2 = (base + 2 < NN) ? cnt[base + 2] : 0;
    int v3 = (base + 3 < NN) ? cnt[base + 3] : 0;
    int s = v0 + v1 + v2 + v3;
    int x = s;
#pragma unroll
    for (int o = 1; o < 32; o <<= 1) {
        int y = __shfl_up_sync(0xffffffffu, x, o);
        if (lane >= o) x += y;
    }
    if (lane == 31) wsum[w] = x;
    __syncthreads();
    if (tid == 0) {
        int r = 0;
#pragma unroll
        for (int j = 0; j < 8; j++) { int t = wsum[j]; wsum[j] = r; r += t; }
        bsum[blockIdx.x] = r;
    }
    __syncthreads();
    int ex = wsum[w] + x - s;
    if (base + 0 < NN) off[base + 0] = ex;
    if (base + 1 < NN) off[base + 1] = ex + v0;
    if (base + 2 < NN) off[base + 2] = ex + v0 + v1;
    if (base + 3 < NN) off[base + 3] = ex + v0 + v1 + v2;
}

__global__ __launch_bounds__(256) void k_scan2(int* __restrict__ bsum, int nb) {
    __shared__ int sm[256];
    int tid = threadIdx.x;
    int v = (tid < nb) ? bsum[tid] : 0;
    sm[tid] = v;
    __syncthreads();
#pragma unroll
    for (int o = 1; o < 256; o <<= 1) {
        int t = (tid >= o) ? sm[tid - o] : 0;
        __syncthreads();
        sm[tid] += t;
        __syncthreads();
    }
    if (tid < nb) bsum[tid] = sm[tid] - v;
}

__global__ __launch_bounds__(256) void k_scan3(int* __restrict__ off,
                                               const int* __restrict__ bsum) {
    int add = bsum[blockIdx.x];
    int base = blockIdx.x * 1024 + threadIdx.x * 4;
#pragma unroll
    for (int i = 0; i < 4; i++)
        if (base + i < NN) off[base + i] += add;
}

// ---------------- CSR placement with per-edge norms ----------------
__global__ __launch_bounds__(256) void k_place(const int* __restrict__ ei) {
    int e = blockIdx.x * 256 + threadIdx.x;
    if (e >= NE) return;
    int a = __ldg(ei + e);
    int b = __ldg(ei + NE + e);
    float nf = __ldg(&g_disf[a]) * __ldg(&g_disf[b]);
    float nr = __ldg(&g_disr[b]) * __ldg(&g_disr[a]);
    int pf = g_offF[b] + atomicAdd(&g_fillF[b], 1);
    g_csrF[pf] = make_int2(a, __float_as_int(nf));
    int pr = g_offR[a] + atomicAdd(&g_fillR[a], 1);
    g_csrR[pr] = make_int2(b, __float_as_int(nr));
}

// ---------------- encoder stage 1 ----------------
template<int KIN, int KOUT, int NPB>
__global__ __launch_bounds__(256) void k_encA(
    const float* __restrict__ x, const float* __restrict__ W,
    const float* __restrict__ bias, float* __restrict__ tmp, int nNodes)
{
    __shared__ float xs[NPB * KIN];
    int tid = threadIdx.x;
    int base = blockIdx.x * NPB;
    const int NSUB = 256 / KOUT;
#pragma unroll
    for (int i = 0; i < (NPB * KIN + 255) / 256; i++) {
        int idx = tid + i * 256;
        if (idx < NPB * KIN) {
            size_t gidx = (size_t)base * KIN + idx;
            size_t mx = (size_t)nNodes * KIN - 1;
            xs[idx] = x[gidx <= mx ? gidx : mx];
        }
    }
    int j = tid & (KOUT - 1);
    int nsub = tid / KOUT;
    float wcol[KIN];
#pragma unroll
    for (int k = 0; k < KIN; k++) wcol[k] = W[k * KOUT + j];
    float bj = bias[j];
    __syncthreads();
#pragma unroll
    for (int t = 0; t < NPB / NSUB; t++) {
        int n = nsub + t * NSUB;
        float a = bj;
#pragma unroll
        for (int k4 = 0; k4 < KIN; k4 += 4) {
            float4 xv = *(const float4*)&xs[n * KIN + k4];
            a += xv.x * wcol[k4] + xv.y * wcol[k4 + 1]
               + xv.z * wcol[k4 + 2] + xv.w * wcol[k4 + 3];
        }
        if (base + n < nNodes)
            tmp[(size_t)(base + n) * KOUT + j] = leaky(a);
    }
}

// ---------------- register-tiled GEMM (encoders): dst = act(src @ W + b) ----------------
template<int KTOT, bool LEAKY>
__global__ __launch_bounds__(128) void k_mm(
    const float* __restrict__ src, int srcStride, int srcOff, int srcBase,
    const float* __restrict__ W, const float* __restrict__ bias,
    float* __restrict__ dst, int dstStride, int dstOff, int dstBase,
    int nNodes)
{
    __shared__ float hs[64 * 68];
    __shared__ float ws[64 * 64];
    int tid = threadIdx.x;
    int tb = blockIdx.x * 64;
    int tx = tid & 15, ty = tid >> 4;
    int bn = ty * 8;
    unsigned long long acc[4][4];
#pragma unroll
    for (int a = 0; a < 4; a++)
#pragma unroll
        for (int b = 0; b < 4; b++) acc[a][b] = 0ull;

    int c = tid & 63, r = tid >> 6;
    for (int kc = 0; kc < KTOT; kc += 64) {
        if (kc) __syncthreads();
#pragma unroll
        for (int i = 0; i < 32; i++)
            ws[tid + i * 128] = W[kc * 64 + tid + i * 128];
#pragma unroll
        for (int i = 0; i < 32; i++) {
            int nl = i * 2 + r;
            int g = tb + nl; if (g >= nNodes) g = nNodes - 1;
            hs[c * 68 + nl] = src[(size_t)(srcBase + g) * srcStride + srcOff + kc + c];
        }
        __syncthreads();
#pragma unroll 4
        for (int k = 0; k < 64; k++) {
            float4 wf = *(const float4*)&ws[k * 64 + tx * 4];
            unsigned long long dw0 = dup64(wf.x);
            unsigned long long dw1 = dup64(wf.y);
            unsigned long long dw2 = dup64(wf.z);
            unsigned long long dw3 = dup64(wf.w);
            ulonglong2 hA = *(const ulonglong2*)&hs[k * 68 + bn];
            ulonglong2 hB = *(const ulonglong2*)&hs[k * 68 + bn + 4];
            fma2(acc[0][0], hA.x, dw0); fma2(acc[0][1], hA.x, dw1);
            fma2(acc[0][2], hA.x, dw2); fma2(acc[0][3], hA.x, dw3);
            fma2(acc[1][0], hA.y, dw0); fma2(acc[1][1], hA.y, dw1);
            fma2(acc[1][2], hA.y, dw2); fma2(acc[1][3], hA.y, dw3);
            fma2(acc[2][0], hB.x, dw0); fma2(acc[2][1], hB.x, dw1);
            fma2(acc[2][2], hB.x, dw2); fma2(acc[2][3], hB.x, dw3);
            fma2(acc[3][0], hB.y, dw0); fma2(acc[3][1], hB.y, dw1);
            fma2(acc[3][2], hB.y, dw2); fma2(acc[3][3], hB.y, dw3);
        }
    }
    float4 bv = *(const float4*)&bias[tx * 4];
#pragma unroll
    for (int np = 0; np < 4; np++) {
        int n0 = tb + bn + np * 2;
        float2 v0 = up64(acc[np][0]);
        float2 v1 = up64(acc[np][1]);
        float2 v2 = up64(acc[np][2]);
        float2 v3 = up64(acc[np][3]);
        float4 o0 = make_float4(v0.x + bv.x, v1.x + bv.y, v2.x + bv.z, v3.x + bv.w);
        float4 o1 = make_float4(v0.y + bv.x, v1.y + bv.y, v2.y + bv.z, v3.y + bv.w);
        if (LEAKY) {
            o0 = make_float4(leaky(o0.x), leaky(o0.y), leaky(o0.z), leaky(o0.w));
            o1 = make_float4(leaky(o1.x), leaky(o1.y), leaky(o1.z), leaky(o1.w));
        }
        if (n0 < nNodes)
            *(float4*)&dst[(size_t)(dstBase + n0) * dstStride + dstOff + tx * 4] = o0;
        if (n0 + 1 < nNodes)
            *(float4*)&dst[(size_t)(dstBase + n0 + 1) * dstStride + dstOff + tx * 4] = o1;
    }
}

// ---------------- fused dual conv GEMM v2: 128-node tile, 8n x 8o per thread ----
__global__ __launch_bounds__(128) void k_mm2(
    const float* __restrict__ src, int srcOff,
    const float* __restrict__ Wf, const float* __restrict__ bf,
    const float* __restrict__ Wr, const float* __restrict__ br)
{
    __shared__ float hs[64 * 132];   // hs[k*132 + node], 128 nodes/tile
    __shared__ float ws[32 * 64];    // 32-k chunk of W
    int tid = threadIdx.x;
    int tb = blockIdx.x * 128;
    int tx = tid & 7;          // outs tx*8 .. tx*8+7
    int ty = tid >> 3;         // nodes ty*8 .. ty*8+7
    int bn = ty * 8;
    // load h tile (transposed): each thread 64 coalesced LDG.32
    {
        int c = tid & 63, r = tid >> 6;
#pragma unroll 8
        for (int i = 0; i < 64; i++) {
            int nl = i * 2 + r;
            int g = tb + nl; if (g >= NN) g = NN - 1;
            hs[c * 132 + nl] = src[(size_t)g * 256 + srcOff + c];
        }
    }
#pragma unroll 1
    for (int ph = 0; ph < 2; ph++) {
        const float* W    = ph ? Wr : Wf;
        const float* bias = ph ? br : bf;
        float*       dst  = ph ? g_xr : g_xf;
        __half2*     yout = ph ? g_yr : g_yf;
        unsigned long long acc[4][8];
#pragma unroll
        for (int p = 0; p < 4; p++)
#pragma unroll
            for (int j = 0; j < 8; j++) acc[p][j] = 0ull;
#pragma unroll 1
        for (int kc = 0; kc < 64; kc += 32) {
            __syncthreads();
#pragma unroll
            for (int i = 0; i < 16; i++)
                ws[tid + i * 128] = W[kc * 64 + tid + i * 128];
            __syncthreads();
#pragma unroll 4
            for (int k = 0; k < 32; k++) {
                const float* hrow = &hs[(kc + k) * 132 + bn];
                ulonglong2 hA = *(const ulonglong2*)(hrow);
                ulonglong2 hB = *(const ulonglong2*)(hrow + 4);
                float4 w0 = *(const float4*)&ws[k * 64 + tx * 8];
                float4 w1 = *(const float4*)&ws[k * 64 + tx * 8 + 4];
                unsigned long long d0 = dup64(w0.x), d1 = dup64(w0.y);
                unsigned long long d2 = dup64(w0.z), d3 = dup64(w0.w);
                unsigned long long d4 = dup64(w1.x), d5 = dup64(w1.y);
                unsigned long long d6 = dup64(w1.z), d7 = dup64(w1.w);
                fma2(acc[0][0], hA.x, d0); fma2(acc[0][1], hA.x, d1);
                fma2(acc[0][2], hA.x, d2); fma2(acc[0][3], hA.x, d3);
                fma2(acc[0][4], hA.x, d4); fma2(acc[0][5], hA.x, d5);
                fma2(acc[0][6], hA.x, d6); fma2(acc[0][7], hA.x, d7);
                fma2(acc[1][0], hA.y, d0); fma2(acc[1][1], hA.y, d1);
                fma2(acc[1][2], hA.y, d2); fma2(acc[1][3], hA.y, d3);
                fma2(acc[1][4], hA.y, d4); fma2(acc[1][5], hA.y, d5);
                fma2(acc[1][6], hA.y, d6); fma2(acc[1][7], hA.y, d7);
                fma2(acc[2][0], hB.x, d0); fma2(acc[2][1], hB.x, d1);
                fma2(acc[2][2], hB.x, d2); fma2(acc[2][3], hB.x, d3);
                fma2(acc[2][4], hB.x, d4); fma2(acc[2][5], hB.x, d5);
                fma2(acc[2][6], hB.x, d6); fma2(acc[2][7], hB.x, d7);
                fma2(acc[3][0], hB.y, d0); fma2(acc[3][1], hB.y, d1);
                fma2(acc[3][2], hB.y, d2); fma2(acc[3][3], hB.y, d3);
                fma2(acc[3][4], hB.y, d4); fma2(acc[3][5], hB.y, d5);
                fma2(acc[3][6], hB.y, d6); fma2(acc[3][7], hB.y, d7);
            }
        }
        float4 bva = *(const float4*)&bias[tx * 8];
        float4 bvb = *(const float4*)&bias[tx * 8 + 4];
#pragma unroll
        for (int p = 0; p < 4; p++) {
            int n0 = tb + bn + p * 2;
            float2 u0 = up64(acc[p][0]), u1 = up64(acc[p][1]);
            float2 u2 = up64(acc[p][2]), u3 = up64(acc[p][3]);
            float2 u4 = up64(acc[p][4]), u5 = up64(acc[p][5]);
            float2 u6 = up64(acc[p][6]), u7 = up64(acc[p][7]);
            float4 ea = make_float4(u0.x + bva.x, u1.x + bva.y, u2.x + bva.z, u3.x + bva.w);
            float4 eb = make_float4(u4.x + bvb.x, u5.x + bvb.y, u6.x + bvb.z, u7.x + bvb.w);
            float4 oa = make_float4(u0.y + bva.x, u1.y + bva.y, u2.y + bva.z, u3.y + bva.w);
            float4 ob = make_float4(u4.y + bvb.x, u5.y + bvb.y, u6.y + bvb.z, u7.y + bvb.w);
            if (n0 < NN) {
                *(float4*)&dst[(size_t)n0 * 64 + tx * 8] = ea;
                *(float4*)&dst[(size_t)n0 * 64 + tx * 8 + 4] = eb;
                __half2 h0 = __float22half2_rn(make_float2(fmaxf(ea.x, 0.f), fmaxf(ea.y, 0.f)));
                __half2 h1 = __float22half2_rn(make_float2(fmaxf(ea.z, 0.f), fmaxf(ea.w, 0.f)));
                __half2 h2 = __float22half2_rn(make_float2(fmaxf(eb.x, 0.f), fmaxf(eb.y, 0.f)));
                __half2 h3 = __float22half2_rn(make_float2(fmaxf(eb.z, 0.f), fmaxf(eb.w, 0.f)));
                uint4 pk = make_uint4(*(unsigned*)&h0, *(unsigned*)&h1,
                                      *(unsigned*)&h2, *(unsigned*)&h3);
                *(uint4*)&yout[(size_t)n0 * 32 + tx * 4] = pk;
            }
            if (n0 + 1 < NN) {
                *(float4*)&dst[(size_t)(n0 + 1) * 64 + tx * 8] = oa;
                *(float4*)&dst[(size_t)(n0 + 1) * 64 + tx * 8 + 4] = ob;
                __half2 h0 = __float22half2_rn(make_float2(fmaxf(oa.x, 0.f), fmaxf(oa.y, 0.f)));
                __half2 h1 = __float22half2_rn(make_float2(fmaxf(oa.z, 0.f), fmaxf(oa.w, 0.f)));
                __half2 h2 = __float22half2_rn(make_float2(fmaxf(ob.x, 0.f), fmaxf(ob.y, 0.f)));
                __half2 h3 = __float22half2_rn(make_float2(fmaxf(ob.z, 0.f), fmaxf(ob.w, 0.f)));
                uint4 pk = make_uint4(*(unsigned*)&h0, *(unsigned*)&h1,
                                      *(unsigned*)&h2, *(unsigned*)&h3);
                *(uint4*)&yout[(size_t)(n0 + 1) * 32 + tx * 4] = pk;
            }
        }
    }
}

// ---------------- fused aggregation (fwd + rev) + self terms + LayerNorm + leaky ----------------
__global__ __launch_bounds__(256) void k_agg(
    const float* __restrict__ rootf, const float* __restrict__ rootr,
    const float* __restrict__ lg, const float* __restrict__ lb,
    float* __restrict__ out, int off)
{
    int n = blockIdx.x * 8 + (threadIdx.x >> 5);
    int lane = threadIdx.x & 31;
    int d = lane * 2;
    int begF = g_offF[n], degF = g_cntr[n];   // fwd buckets keyed by col
    int begR = g_offR[n], degR = g_cntf[n];   // rev buckets keyed by row
    float2 af = make_float2(0.f, 0.f);
    float2 ar = make_float2(0.f, 0.f);
    {
        const int2* cs = g_csrF + begF;
        const __half2* Y = g_yf;
        int i = 0;
        for (; i + 4 <= degF; i += 4) {
            int2 e0 = __ldg(cs + i), e1 = __ldg(cs + i + 1);
            int2 e2 = __ldg(cs + i + 2), e3 = __ldg(cs + i + 3);
            float2 v0 = __half22float2(__ldg(Y + (size_t)e0.x * 32 + lane));
            float2 v1 = __half22float2(__ldg(Y + (size_t)e1.x * 32 + lane));
            float2 v2 = __half22float2(__ldg(Y + (size_t)e2.x * 32 + lane));
            float2 v3 = __half22float2(__ldg(Y + (size_t)e3.x * 32 + lane));
            float n0 = __int_as_float(e0.y), n1 = __int_as_float(e1.y);
            float n2 = __int_as_float(e2.y), n3 = __int_as_float(e3.y);
            af.x += v0.x * n0 + v1.x * n1 + v2.x * n2 + v3.x * n3;
            af.y += v0.y * n0 + v1.y * n1 + v2.y * n2 + v3.y * n3;
        }
        for (; i < degF; i++) {
            int2 e0 = __ldg(cs + i);
            float2 v0 = __half22float2(__ldg(Y + (size_t)e0.x * 32 + lane));
            float n0 = __int_as_float(e0.y);
            af.x += v0.x * n0;
            af.y += v0.y * n0;
        }
    }
    {
        const int2* cs = g_csrR + begR;
        const __half2* Y = g_yr;
        int i = 0;
        for (; i + 4 <= degR; i += 4) {
            int2 e0 = __ldg(cs + i), e1 = __ldg(cs + i + 1);
            int2 e2 = __ldg(cs + i + 2), e3 = __ldg(cs + i + 3);
            float2 v0 = __half22float2(__ldg(Y + (size_t)e0.x * 32 + lane));
            float2 v1 = __half22float2(__ldg(Y + (size_t)e1.x * 32 + lane));
            float2 v2 = __half22float2(__ldg(Y + (size_t)e2.x * 32 + lane));
            float2 v3 = __half22float2(__ldg(Y + (size_t)e3.x * 32 + lane));
            float n0 = __int_as_float(e0.y), n1 = __int_as_float(e1.y);
            float n2 = __int_as_float(e2.y), n3 = __int_as_float(e3.y);
            ar.x += v0.x * n0 + v1.x * n1 + v2.x * n2 + v3.x * n3;
            ar.y += v0.y * n0 + v1.y * n1 + v2.y * n2 + v3.y * n3;
        }
        for (; i < degR; i++) {
            int2 e0 = __ldg(cs + i);
            float2 v0 = __half22float2(__ldg(Y + (size_t)e0.x * 32 + lane));
            float n0 = __int_as_float(e0.y);
            ar.x += v0.x * n0;
            ar.y += v0.y * n0;
        }
    }
    size_t o64 = (size_t)n * 64 + d;
    float2 fx = *(const float2*)&g_xf[o64];
    float2 rx = *(const float2*)&g_xr[o64];
    float idf = g_idegf[n], idr = g_idegr[n];
    float s0 = af.x + ar.x + fmaxf(fx.x + rootf[d], 0.f) * idf
                           + fmaxf(rx.x + rootr[d], 0.f) * idr;
    float s1 = af.y + ar.y + fmaxf(fx.y + rootf[d + 1], 0.f) * idf
                           + fmaxf(rx.y + rootr[d + 1], 0.f) * idr;
    float sum = s0 + s1;
#pragma unroll
    for (int o = 16; o > 0; o >>= 1) sum += __shfl_xor_sync(0xffffffffu, sum, o);
    float m = sum * (1.0f / 64.0f);
    float d0 = s0 - m, d1 = s1 - m;
    float sq = d0 * d0 + d1 * d1;
#pragma unroll
    for (int o = 16; o > 0; o >>= 1) sq += __shfl_xor_sync(0xffffffffu, sq, o);
    float inv = rsqrtf(sq * (1.0f / 64.0f) + 1e-5f);
    float o0 = leaky(d0 * inv * lg[d] + lb[d]);
    float o1 = leaky(d1 * inv * lg[d + 1] + lb[d + 1]);
    *(float2*)&out[(size_t)n * 256 + off + d] = make_float2(o0, o1);
}

// ---------------- launch ----------------
extern "C" void kernel_launch(void* const* d_in, const int* in_sizes, int n_in,
                              void* d_out, int out_size) {
    const float* x     = (const float*)d_in[0];
    const float* xnet  = (const float*)d_in[1];
    const int*   ei    = (const int*)  d_in[2];
    const float* e1W   = (const float*)d_in[3];
    const float* e1b   = (const float*)d_in[4];
    const float* e2W   = (const float*)d_in[5];
    const float* e2b   = (const float*)d_in[6];
    const float* n1W   = (const float*)d_in[7];
    const float* n1b   = (const float*)d_in[8];
    const float* n2W   = (const float*)d_in[9];
    const float* n2b   = (const float*)d_in[10];
    const float* convW = (const float*)d_in[11];
    const float* convb = (const float*)d_in[12];
    const float* convr = (const float*)d_in[13];
    const float* reW   = (const float*)d_in[14];
    const float* reb   = (const float*)d_in[15];
    const float* rer   = (const float*)d_in[16];
    const float* lng   = (const float*)d_in[17];
    const float* lnb   = (const float*)d_in[18];
    float* out = (float*)d_out;

    void *pcf, *pcr, *pff, *pfr, *poF, *poR, *pbF, *pbR, *ptmp, *ptmpn;
    cudaGetSymbolAddress(&pcf, g_cntf);
    cudaGetSymbolAddress(&pcr, g_cntr);
    cudaGetSymbolAddress(&pff, g_fillF);
    cudaGetSymbolAddress(&pfr, g_fillR);
    cudaGetSymbolAddress(&poF, g_offF);
    cudaGetSymbolAddress(&poR, g_offR);
    cudaGetSymbolAddress(&pbF, g_bsF);
    cudaGetSymbolAddress(&pbR, g_bsR);
    cudaGetSymbolAddress(&ptmp, g_tmp);
    cudaGetSymbolAddress(&ptmpn, g_tmpn);

    static cudaStream_t s2 = []() {
        cudaStream_t s; cudaStreamCreateWithFlags(&s, cudaStreamNonBlocking); return s;
    }();
    static cudaStream_t s3 = []() {
        cudaStream_t s; cudaStreamCreateWithFlags(&s, cudaStreamNonBlocking); return s;
    }();
    auto mkev = []() { cudaEvent_t e; cudaEventCreateWithFlags(&e, cudaEventDisableTiming); return e; };
    static cudaEvent_t evF = mkev();
    static cudaEvent_t evCSR = mkev();
    static cudaEvent_t evNet = mkev();

    cudaEventRecord(evF, 0);

    // ---- s2: CSR build (overlaps encoders) ----
    cudaStreamWaitEvent(s2, evF, 0);
    cudaMemsetAsync(pcf, 0, NN * sizeof(int), s2);
    cudaMemsetAsync(pcr, 0, NN * sizeof(int), s2);
    cudaMemsetAsync(pff, 0, NN * sizeof(int), s2);
    cudaMemsetAsync(pfr, 0, NN * sizeof(int), s2);
    k_count<<<(NE + 255) / 256, 256, 0, s2>>>(ei);
    k_deg<<<(NN + 255) / 256, 256, 0, s2>>>();
    k_scan1<<<NSCANB, 256, 0, s2>>>((const int*)pcr, (int*)poF, (int*)pbF);
    k_scan1<<<NSCANB, 256, 0, s2>>>((const int*)pcf, (int*)poR, (int*)pbR);
    k_scan2<<<1, 256, 0, s2>>>((int*)pbF, NSCANB);
    k_scan2<<<1, 256, 0, s2>>>((int*)pbR, NSCANB);
    k_scan3<<<NSCANB, 256, 0, s2>>>((int*)poF, (const int*)pbF);
    k_scan3<<<NSCANB, 256, 0, s2>>>((int*)poR, (const int*)pbR);
    k_place<<<(NE + 255) / 256, 256, 0, s2>>>(ei);
    cudaEventRecord(evCSR, s2);

    // ---- s3: net encoder (independent of inst encoder) ----
    cudaStreamWaitEvent(s3, evF, 0);
    k_encA<8, 64, 32><<<(N_NETN + 31) / 32, 256, 0, s3>>>(
        xnet, n1W, n1b, (float*)ptmpn, N_NETN);
    k_mm<64, true><<<(N_NETN + 63) / 64, 128, 0, s3>>>(
        (const float*)ptmpn, 64, 0, 0, n2W, n2b, out, 256, 0, N_INST, N_NETN);
    cudaEventRecord(evNet, s3);

    // ---- main: inst encoder ----
    k_encA<16, 128, 32><<<N_INST / 32, 256>>>(x, e1W, e1b, (float*)ptmp, N_INST);
    k_mm<128, true><<<(N_INST + 63) / 64, 128>>>(
        (const float*)ptmp, 128, 0, 0, e2W, e2b, out, 256, 0, 0, N_INST);

    // ---- layers: fused dual GEMM -> fused agg ----
    cudaStreamWaitEvent(0, evNet, 0);
    cudaStreamWaitEvent(0, evCSR, 0);
    for (int l = 0; l < 3; l++) {
        k_mm2<<<(NN + 127) / 128, 128>>>(
            out, l * 64,
            convW + l * 4096, convb + l * 64,
            reW + l * 4096,   reb + l * 64);
        k_agg<<<NN / 8, 256>>>(convr + l * 64, rer + l * 64,
                               lng + l * 64, lnb + l * 64,
                               out, (l + 1) * 64);
    }
}